// round 7
// baseline (speedup 1.0000x reference)
#include <cuda_runtime.h>
#include <math.h>
#include <stdint.h>

#define Bq   4096
#define Nn   10
#define DIN  32
#define Dd   128
#define PHId 256
#define RHOd 128
#define Ll   3
#define EPS  1e-5f
#define LDA  132      // smem activation row stride (floats)

typedef unsigned long long u64;

__device__ __forceinline__ u64 pk2(float lo, float hi){ u64 r; asm("mov.b64 %0,{%1,%2};":"=l"(r):"f"(lo),"f"(hi)); return r; }
__device__ __forceinline__ void upk2(float& lo, float& hi, u64 v){ asm("mov.b64 {%0,%1},%2;":"=f"(lo),"=f"(hi):"l"(v)); }
__device__ __forceinline__ u64 fma2(u64 a,u64 b,u64 c){ u64 d; asm("fma.rn.f32x2 %0,%1,%2,%3;":"=l"(d):"l"(a),"l"(b),"l"(c)); return d; }
__device__ __forceinline__ uint32_t cvt_tf32(float x){ uint32_t r; asm("cvt.rna.tf32.f32 %0,%1;":"=r"(r):"f"(x)); return r; }

__device__ __forceinline__ void mma_tf32(float c[4], uint32_t a0,uint32_t a1,uint32_t a2,uint32_t a3,
                                         uint32_t b0,uint32_t b1){
    asm("mma.sync.aligned.m16n8k8.row.col.f32.tf32.tf32.f32 "
        "{%0,%1,%2,%3},{%4,%5,%6,%7},{%8,%9},{%0,%1,%2,%3};"
        : "+f"(c[0]),"+f"(c[1]),"+f"(c[2]),"+f"(c[3])
        : "r"(a0),"r"(a1),"r"(a2),"r"(a3),"r"(b0),"r"(b1));
}

// C[NT][4] += As(16 x 8*KT, smem node-major) @ W(8*KT x ldw, global row-major),
// warp covers output cols [wbase, wbase + 8*NT)
template<int KT,int NT>
__device__ __forceinline__ void warp_gemm(const float* __restrict__ As,
                                          const float* __restrict__ W, int ldw,
                                          int wbase, int g, int tg, float C[][4])
{
    #pragma unroll
    for(int kt=0;kt<KT;++kt){
        const int k0 = kt*8+tg;
        uint32_t a0 = cvt_tf32(As[g*LDA+k0]);
        uint32_t a1 = cvt_tf32(As[(g+8)*LDA+k0]);
        uint32_t a2 = cvt_tf32(As[g*LDA+k0+4]);
        uint32_t a3 = cvt_tf32(As[(g+8)*LDA+k0+4]);
        const float* Wk  = W + (size_t)k0*ldw + wbase + g;
        const float* Wk4 = Wk + 4*(size_t)ldw;
        #pragma unroll
        for(int nt=0;nt<NT;++nt){
            uint32_t b0 = cvt_tf32(Wk[nt*8]);
            uint32_t b1 = cvt_tf32(Wk4[nt*8]);
            mma_tf32(C[nt],a0,a1,a2,a3,b0,b1);
        }
    }
}

#define ZERO_C(C,NT) { _Pragma("unroll") for(int _n=0;_n<NT;++_n){ (C)[_n][0]=0.f;(C)[_n][1]=0.f;(C)[_n][2]=0.f;(C)[_n][3]=0.f; } }

__global__ __launch_bounds__(128)
void gcn_deepset_kernel(
    const float* __restrict__ A, const float* __restrict__ X,
    const int* __restrict__ home,
    const float* __restrict__ We1, const float* __restrict__ be1,
    const float* __restrict__ We2, const float* __restrict__ be2,
    const float* __restrict__ rgcn_w, const float* __restrict__ rgcn_root,
    const float* __restrict__ rgcn_b,
    const float* __restrict__ l1w, const float* __restrict__ l1b,
    const float* __restrict__ l2w, const float* __restrict__ l2b,
    const float* __restrict__ ln_g, const float* __restrict__ ln_b,
    const float* __restrict__ p1w, const float* __restrict__ p1b,
    const float* __restrict__ p2w, const float* __restrict__ p2b,
    const float* __restrict__ r1w, const float* __restrict__ r1b,
    const float* __restrict__ r2w, const float* __restrict__ r2b,
    float* __restrict__ out)
{
    __shared__ __align__(16) float sH [16*LDA];
    __shared__ __align__(16) float sB1[16*LDA];
    __shared__ __align__(16) float sB2[16*LDA];
    __shared__ __align__(16) float sB3[16*LDA];
    __shared__ __align__(8)  float2 sM[3][Nn][5];   // M0,M1,Mr packed over node-pairs i
    __shared__ float sRawA[Nn*Nn], sR0[Nn], sR1[Nn];
    __shared__ __align__(16) float sHS[PHId], sAWS[PHId];
    __shared__ float sMu[Nn], sRstd[Nn], sRed[8];
    __shared__ float sMk[16], sMa[16];

    const int b    = blockIdx.x;
    const int tid  = threadIdx.x;        // 0..127
    const int warp = tid >> 5;
    const int lane = tid & 31;
    const int g    = lane >> 2;          // fragment row group 0..7
    const int tg   = lane & 3;           // thread-in-group 0..3
    const int wb32 = warp * 32;          // warp col base for 128-wide outputs
    const int wb64 = warp * 64;          // for 256-wide outputs

    // ---- phase 0: raw A, zero X buffer, masks ----
    for (int idx = tid; idx < Nn*Nn; idx += 128) sRawA[idx] = A[b*Nn*Nn + idx];
    for (int idx = tid; idx < 16*LDA; idx += 128) sB1[idx] = 0.f;
    if (tid < 16) {
        int hm = (tid < Nn) ? home[b*Nn + tid] : 0;
        sMk[tid] = (tid < Nn) ? (float)hm : 0.f;
        sMa[tid] = (tid < Nn) ? 1.f - (float)hm : 0.f;
    }
    __syncthreads();

    // ---- phase 1: X into sB1 (node-major), relation counts ----
    for (int idx = tid; idx < Nn*DIN; idx += 128)
        sB1[(idx/DIN)*LDA + (idx%DIN)] = X[b*Nn*DIN + idx];
    if (tid < Nn) {
        int j = tid, c1 = 0;
        #pragma unroll
        for (int i = 0; i < Nn; ++i) c1 += (sRawA[i*Nn + j] > 0.f);
        sR1[j] = 1.f / fmaxf((float)c1, 1.f);
        sR0[j] = 1.f / fmaxf((float)(Nn - c1), 1.f);
    }
    __syncthreads();

    // ---- phase 2: M matrices (column t per thread) ----
    if (tid < Nn) {
        int t = tid;
        float m0c[Nn], m1c[Nn], mrc[Nn];
        #pragma unroll
        for (int i = 0; i < Nn; ++i) { m0c[i] = 0.f; m1c[i] = 0.f; }
        #pragma unroll
        for (int j = 0; j < Nn; ++j) {
            bool pos = sRawA[t*Nn + j] > 0.f;
            float cf0 = pos ? 0.f : sR0[j];
            float cf1 = pos ? sR1[j] : 0.f;
            #pragma unroll
            for (int i = 0; i < Nn; ++i) {
                float aij = fabsf(sRawA[i*Nn + j]);
                m0c[i] += aij * cf0;
                m1c[i] += aij * cf1;
            }
        }
        #pragma unroll
        for (int i = 0; i < Nn; ++i) mrc[i] = fabsf(sRawA[i*Nn + t]);
        #pragma unroll
        for (int ip = 0; ip < 5; ++ip) {
            sM[0][t][ip] = make_float2(m0c[2*ip], m0c[2*ip+1]);
            sM[1][t][ip] = make_float2(m1c[2*ip], m1c[2*ip+1]);
            sM[2][t][ip] = make_float2(mrc[2*ip], mrc[2*ip+1]);
        }
    }

    const float gT = ln_g[tid & 127], bT = ln_b[tid & 127];   // per-col LN params (col = tid)

    float C4[4][4];

    // ---- embed1: relu(X@We1 + be1) -> sB2 ----
    ZERO_C(C4,4);
    warp_gemm<4,4>(sB1, We1, Dd, wb32, g, tg, C4);
    #pragma unroll
    for (int nt = 0; nt < 4; ++nt) {
        int col = wb32 + nt*8 + 2*tg;
        float2 bb = *(const float2*)&be1[col];
        *(float2*)&sB2[g*LDA + col]     = make_float2(fmaxf(C4[nt][0]+bb.x,0.f), fmaxf(C4[nt][1]+bb.y,0.f));
        *(float2*)&sB2[(g+8)*LDA + col] = make_float2(fmaxf(C4[nt][2]+bb.x,0.f), fmaxf(C4[nt][3]+bb.y,0.f));
    }
    __syncthreads();

    // ---- embed2: (T@We2 + be2) -> sH ----
    ZERO_C(C4,4);
    warp_gemm<16,4>(sB2, We2, Dd, wb32, g, tg, C4);
    #pragma unroll
    for (int nt = 0; nt < 4; ++nt) {
        int col = wb32 + nt*8 + 2*tg;
        float2 bb = *(const float2*)&be2[col];
        *(float2*)&sH[g*LDA + col]     = make_float2(C4[nt][0]+bb.x, C4[nt][1]+bb.y);
        *(float2*)&sH[(g+8)*LDA + col] = make_float2(C4[nt][2]+bb.x, C4[nt][3]+bb.y);
    }
    __syncthreads();

    // ---- GNN layers ----
    for (int l = 0; l < Ll; ++l) {
        const float* W0 = rgcn_w    + (size_t)(l*2+0)*Dd*Dd;
        const float* W1 = rgcn_w    + (size_t)(l*2+1)*Dd*Dd;
        const float* Wr = rgcn_root + (size_t)l*Dd*Dd;
        const float* rb = rgcn_b    + l*Dd;

        // Y0 = H@W0 -> sB1
        ZERO_C(C4,4);
        warp_gemm<16,4>(sH, W0, Dd, wb32, g, tg, C4);
        #pragma unroll
        for (int nt = 0; nt < 4; ++nt) {
            int col = wb32 + nt*8 + 2*tg;
            *(float2*)&sB1[g*LDA + col]     = make_float2(C4[nt][0], C4[nt][1]);
            *(float2*)&sB1[(g+8)*LDA + col] = make_float2(C4[nt][2], C4[nt][3]);
        }
        // Y1 = H@W1 -> sB2
        ZERO_C(C4,4);
        warp_gemm<16,4>(sH, W1, Dd, wb32, g, tg, C4);
        #pragma unroll
        for (int nt = 0; nt < 4; ++nt) {
            int col = wb32 + nt*8 + 2*tg;
            *(float2*)&sB2[g*LDA + col]     = make_float2(C4[nt][0], C4[nt][1]);
            *(float2*)&sB2[(g+8)*LDA + col] = make_float2(C4[nt][2], C4[nt][3]);
        }
        // Yr = H@Wr + b -> sB3
        ZERO_C(C4,4);
        warp_gemm<16,4>(sH, Wr, Dd, wb32, g, tg, C4);
        #pragma unroll
        for (int nt = 0; nt < 4; ++nt) {
            int col = wb32 + nt*8 + 2*tg;
            float2 bb = *(const float2*)&rb[col];
            *(float2*)&sB3[g*LDA + col]     = make_float2(C4[nt][0]+bb.x, C4[nt][1]+bb.y);
            *(float2*)&sB3[(g+8)*LDA + col] = make_float2(C4[nt][2]+bb.x, C4[nt][3]+bb.y);
        }
        __syncthreads();

        // node-mix (column-private, col = tid):
        // agg[i] = sum_t M0[i][t]*Y0[t] + M1[i][t]*Y1[t] + Mr[i][t]*Yr[t]
        float aggR[Nn];
        {
            u64 acc[5];
            #pragma unroll
            for (int q = 0; q < 5; ++q) acc[q] = 0;
            #pragma unroll
            for (int t = 0; t < Nn; ++t) {
                float y0 = sB1[t*LDA + tid];
                float y1 = sB2[t*LDA + tid];
                float yr = sB3[t*LDA + tid];
                u64 y0p = pk2(y0,y0), y1p = pk2(y1,y1), yrp = pk2(yr,yr);
                #pragma unroll
                for (int ip = 0; ip < 5; ++ip) {
                    acc[ip] = fma2(*(const u64*)&sM[0][t][ip], y0p, acc[ip]);
                    acc[ip] = fma2(*(const u64*)&sM[1][t][ip], y1p, acc[ip]);
                    acc[ip] = fma2(*(const u64*)&sM[2][t][ip], yrp, acc[ip]);
                }
            }
            #pragma unroll
            for (int ip = 0; ip < 5; ++ip) upk2(aggR[2*ip], aggR[2*ip+1], acc[ip]);
            #pragma unroll
            for (int i = 0; i < Nn; ++i) sB3[i*LDA + tid] = aggR[i];
        }
        __syncthreads();

        // LN stats: warp w owns rows w, w+4, w+8
        for (int r = warp; r < Nn; r += 4) {
            float s = 0.f, q = 0.f;
            #pragma unroll
            for (int u = 0; u < 4; ++u) {
                float x = sB3[r*LDA + lane + 32*u];
                s += x; q += x*x;
            }
            #pragma unroll
            for (int o = 16; o > 0; o >>= 1) {
                s += __shfl_xor_sync(0xffffffffu, s, o);
                q += __shfl_xor_sync(0xffffffffu, q, o);
            }
            if (lane == 0) {
                float mu = s * (1.f/Dd);
                float var = q * (1.f/Dd) - mu*mu;
                sMu[r] = mu; sRstd[r] = rsqrtf(var + EPS);
            }
        }
        __syncthreads();

        // normalize + relu -> sB3 (column-private)
        #pragma unroll
        for (int i = 0; i < Nn; ++i) {
            float y = (aggR[i] - sMu[i]) * sRstd[i] * gT + bT;
            sB3[i*LDA + tid] = fmaxf(y, 0.f);
        }
        __syncthreads();

        // l1: relu(AG@W + b) -> sB1
        ZERO_C(C4,4);
        warp_gemm<16,4>(sB3, l1w + (size_t)l*Dd*Dd, Dd, wb32, g, tg, C4);
        {
            const float* lb = l1b + l*Dd;
            #pragma unroll
            for (int nt = 0; nt < 4; ++nt) {
                int col = wb32 + nt*8 + 2*tg;
                float2 bb = *(const float2*)&lb[col];
                *(float2*)&sB1[g*LDA + col]     = make_float2(fmaxf(C4[nt][0]+bb.x,0.f), fmaxf(C4[nt][1]+bb.y,0.f));
                *(float2*)&sB1[(g+8)*LDA + col] = make_float2(fmaxf(C4[nt][2]+bb.x,0.f), fmaxf(C4[nt][3]+bb.y,0.f));
            }
        }
        __syncthreads();

        // l2: (T@W + b), residual fold: H += result
        ZERO_C(C4,4);
        warp_gemm<16,4>(sB1, l2w + (size_t)l*Dd*Dd, Dd, wb32, g, tg, C4);
        {
            const float* lb = l2b + l*Dd;
            #pragma unroll
            for (int nt = 0; nt < 4; ++nt) {
                int col = wb32 + nt*8 + 2*tg;
                float2 bb = *(const float2*)&lb[col];
                float2 h0 = *(const float2*)&sH[g*LDA + col];
                float2 h1 = *(const float2*)&sH[(g+8)*LDA + col];
                *(float2*)&sH[g*LDA + col]     = make_float2(h0.x + C4[nt][0] + bb.x, h0.y + C4[nt][1] + bb.y);
                *(float2*)&sH[(g+8)*LDA + col] = make_float2(h1.x + C4[nt][2] + bb.x, h1.y + C4[nt][3] + bb.y);
            }
        }
        __syncthreads();
    }

    // ---- phi1: relu(H@p1w + p1b) -> sB1 (cols 0-127) / sB2 (cols 128-255) ----
    float C8[8][4];
    ZERO_C(C8,8);
    warp_gemm<16,8>(sH, p1w, PHId, wb64, g, tg, C8);
    #pragma unroll
    for (int nt = 0; nt < 8; ++nt) {
        int col = wb64 + nt*8 + 2*tg;
        float2 bb = *(const float2*)&p1b[col];
        float* dst = (col < 128) ? sB1 : sB2;
        int cc = col & 127;
        *(float2*)&dst[g*LDA + cc]     = make_float2(fmaxf(C8[nt][0]+bb.x,0.f), fmaxf(C8[nt][1]+bb.y,0.f));
        *(float2*)&dst[(g+8)*LDA + cc] = make_float2(fmaxf(C8[nt][2]+bb.x,0.f), fmaxf(C8[nt][3]+bb.y,0.f));
    }
    __syncthreads();

    // ---- phi2: relu(P@p2w + p2b), masked sums ----
    ZERO_C(C8,8);
    warp_gemm<16,8>(sB1, p2w,             PHId, wb64, g, tg, C8);
    warp_gemm<16,8>(sB2, p2w + 128*PHId,  PHId, wb64, g, tg, C8);
    {
        float mg = sMk[g], mg8 = sMk[g+8];
        float ag = sMa[g], ag8 = sMa[g+8];
        #pragma unroll
        for (int nt = 0; nt < 8; ++nt) {
            int col = wb64 + nt*8 + 2*tg;
            float2 bb = *(const float2*)&p2b[col];
            float r0 = fmaxf(C8[nt][0]+bb.x, 0.f);
            float r1 = fmaxf(C8[nt][1]+bb.y, 0.f);
            float r2 = fmaxf(C8[nt][2]+bb.x, 0.f);
            float r3 = fmaxf(C8[nt][3]+bb.y, 0.f);
            float hs0 = r0*mg + r2*mg8, hs1 = r1*mg + r3*mg8;
            float as0 = r0*ag + r2*ag8, as1 = r1*ag + r3*ag8;
            #pragma unroll
            for (int o = 4; o <= 16; o <<= 1) {
                hs0 += __shfl_xor_sync(0xffffffffu, hs0, o);
                hs1 += __shfl_xor_sync(0xffffffffu, hs1, o);
                as0 += __shfl_xor_sync(0xffffffffu, as0, o);
                as1 += __shfl_xor_sync(0xffffffffu, as1, o);
            }
            if (g == 0) {
                sHS[col] = hs0;  sHS[col+1] = hs1;
                sAWS[col] = as0; sAWS[col+1] = as1;
            }
        }
    }
    __syncthreads();

    // ---- rho(hs) - rho(aws): col = tid (RHO=128) ----
    {
        float acch = r1b[tid], acca = acch;
        const float* W = r1w + tid;
        #pragma unroll 8
        for (int k = 0; k < PHId; k += 4) {
            float4 hv = *(const float4*)&sHS[k];
            float4 av = *(const float4*)&sAWS[k];
            float w0 = W[(k+0)*RHOd], w1 = W[(k+1)*RHOd];
            float w2 = W[(k+2)*RHOd], w3 = W[(k+3)*RHOd];
            acch += hv.x*w0 + hv.y*w1 + hv.z*w2 + hv.w*w3;
            acca += av.x*w0 + av.y*w1 + av.z*w2 + av.w*w3;
        }
        float w2v = r2w[tid];
        float ph = fmaxf(acch, 0.f) * w2v;
        float pa = fmaxf(acca, 0.f) * w2v;
        #pragma unroll
        for (int o = 16; o > 0; o >>= 1) {
            ph += __shfl_down_sync(0xffffffffu, ph, o);
            pa += __shfl_down_sync(0xffffffffu, pa, o);
        }
        if (lane == 0) { sRed[warp] = ph; sRed[4+warp] = pa; }
        __syncthreads();
        if (tid == 0) {
            float dh = sRed[0]+sRed[1]+sRed[2]+sRed[3];
            float da = sRed[4]+sRed[5]+sRed[6]+sRed[7];
            out[b] = 0.5f + 0.5f * tanhf(dh - da);
        }
    }
}

extern "C" void kernel_launch(void* const* d_in, const int* in_sizes, int n_in,
                              void* d_out, int out_size)
{
    const float* A    = (const float*)d_in[0];
    const float* X    = (const float*)d_in[1];
    const int*   home = (const int*)  d_in[2];
    const float* We1  = (const float*)d_in[3];
    const float* be1  = (const float*)d_in[4];
    const float* We2  = (const float*)d_in[5];
    const float* be2  = (const float*)d_in[6];
    const float* rgw  = (const float*)d_in[7];
    const float* rgr  = (const float*)d_in[8];
    const float* rgb  = (const float*)d_in[9];
    const float* l1w  = (const float*)d_in[10];
    const float* l1b  = (const float*)d_in[11];
    const float* l2w  = (const float*)d_in[12];
    const float* l2b  = (const float*)d_in[13];
    const float* lng  = (const float*)d_in[14];
    const float* lnb  = (const float*)d_in[15];
    const float* p1w  = (const float*)d_in[16];
    const float* p1b  = (const float*)d_in[17];
    const float* p2w  = (const float*)d_in[18];
    const float* p2b  = (const float*)d_in[19];
    const float* r1w  = (const float*)d_in[20];
    const float* r1b  = (const float*)d_in[21];
    const float* r2w  = (const float*)d_in[22];
    const float* r2b  = (const float*)d_in[23];

    gcn_deepset_kernel<<<Bq, 128>>>(
        A, X, home, We1, be1, We2, be2, rgw, rgr, rgb,
        l1w, l1b, l2w, l2b, lng, lnb, p1w, p1b, p2w, p2b,
        r1w, r1b, r2w, r2b, (float*)d_out);
    (void)in_sizes; (void)n_in; (void)out_size; (void)r2b;
}

// round 10
// speedup vs baseline: 1.2967x; 1.2967x over previous
#include <cuda_runtime.h>
#include <math.h>
#include <stdint.h>

#define Bq    4096
#define Nn    10
#define BN    40960          // Bq*Nn
#define DIN   32
#define Dd    128
#define PHId  256
#define RHOd  128
#define Ll    3
#define EPS   1e-5f

// ---------------- scratch (static device globals; no allocation) ----------------
__device__ float gH  [BN * Dd];
__device__ float gT1 [BN * Dd];
__device__ float gY0 [BN * Dd];
__device__ float gY1 [BN * Dd];
__device__ float gY2 [BN * Dd];
__device__ float gAgg[BN * Dd];
__device__ float gP1 [BN * PHId];
__device__ float gP2 [BN * PHId];
__device__ float gS  [2 * Bq * PHId];
__device__ float gR  [2 * Bq * RHOd];
__device__ float gMix[Bq * 300];

__device__ __forceinline__ float tfr(float x) {        // round to tf32, keep bits in a float
    uint32_t r; asm("cvt.rna.tf32.f32 %0,%1;" : "=r"(r) : "f"(x));
    return __uint_as_float(r);
}

__device__ __forceinline__ void mma_tf32(float c[4], uint32_t a0, uint32_t a1, uint32_t a2, uint32_t a3,
                                         uint32_t b0, uint32_t b1) {
    asm("mma.sync.aligned.m16n8k8.row.col.f32.tf32.tf32.f32 "
        "{%0,%1,%2,%3},{%4,%5,%6,%7},{%8,%9},{%0,%1,%2,%3};"
        : "+f"(c[0]), "+f"(c[1]), "+f"(c[2]), "+f"(c[3])
        : "r"(a0), "r"(a1), "r"(a2), "r"(a3), "r"(b0), "r"(b1));
}

// ---------------- GEMM core (device inline) ----------------
// Computes the 128x128 CTA tile product into C[2][8][4].
template<int K, int LDB_>
__device__ __forceinline__ void gemm_core(const float* __restrict__ Ag,
                                          const float* __restrict__ Bg,
                                          size_t Rb, int cb,
                                          float (&As)[128][20], float (&Bs)[2][8][136],
                                          float C[2][8][4])
{
    const int tid  = threadIdx.x;
    const int warp = tid >> 5, lane = tid & 31;
    const int g    = lane >> 2, tg = lane & 3;
    const int wr   = (warp >> 1) * 32;
    const int wc   = (warp & 1) * 64;

    const int r_st  = tid >> 1, kk_st = (tid & 1) * 8;
    const int k_st  = tid >> 4, c_st  = (tid & 15) * 8;

    #pragma unroll 1
    for (int ch = 0; ch < K / 16; ++ch) {
        {   // stage A chunk [128 x 16]
            const float* src = Ag + (Rb + r_st) * K + ch * 16 + kk_st;
            float4 v0 = *(const float4*)src, v1 = *(const float4*)(src + 4);
            float* d = &As[r_st][kk_st];
            d[0]=tfr(v0.x); d[1]=tfr(v0.y); d[2]=tfr(v0.z); d[3]=tfr(v0.w);
            d[4]=tfr(v1.x); d[5]=tfr(v1.y); d[6]=tfr(v1.z); d[7]=tfr(v1.w);
        }
        {   // stage B chunk [16 x 128]
            const float* src = Bg + (size_t)(ch * 16 + k_st) * LDB_ + cb + c_st;
            float4 v0 = *(const float4*)src, v1 = *(const float4*)(src + 4);
            float4* d = (float4*)&Bs[k_st >> 3][k_st & 7][c_st];
            d[0] = make_float4(tfr(v0.x), tfr(v0.y), tfr(v0.z), tfr(v0.w));
            d[1] = make_float4(tfr(v1.x), tfr(v1.y), tfr(v1.z), tfr(v1.w));
        }
        __syncthreads();
        #pragma unroll
        for (int kt = 0; kt < 2; ++kt) {
            uint32_t a[2][4];
            #pragma unroll
            for (int mt = 0; mt < 2; ++mt) {
                const int r0 = wr + mt * 16;
                a[mt][0] = __float_as_uint(As[r0 + g    ][kt * 8 + tg    ]);
                a[mt][1] = __float_as_uint(As[r0 + g + 8][kt * 8 + tg    ]);
                a[mt][2] = __float_as_uint(As[r0 + g    ][kt * 8 + tg + 4]);
                a[mt][3] = __float_as_uint(As[r0 + g + 8][kt * 8 + tg + 4]);
            }
            #pragma unroll
            for (int nt = 0; nt < 8; ++nt) {
                uint32_t b0 = __float_as_uint(Bs[kt][tg    ][wc + nt * 8 + g]);
                uint32_t b1 = __float_as_uint(Bs[kt][tg + 4][wc + nt * 8 + g]);
                mma_tf32(C[0][nt], a[0][0], a[0][1], a[0][2], a[0][3], b0, b1);
                mma_tf32(C[1][nt], a[1][0], a[1][1], a[1][2], a[1][3], b0, b1);
            }
        }
        __syncthreads();
    }
}

// ---------------- generic tensor-core GEMM kernel ----------------
template<int K, int NTOT, bool RELU, bool RESID, bool HASBIAS>
__global__ __launch_bounds__(256)
void gemm_tc(const float* __restrict__ Ag, const float* __restrict__ Bg,
             const float* __restrict__ bias, float* __restrict__ Cg)
{
    __shared__ float As[128][20];
    __shared__ float Bs[2][8][136];

    const int tid  = threadIdx.x;
    const int warp = tid >> 5, lane = tid & 31;
    const int g    = lane >> 2, tg = lane & 3;
    const int wr   = (warp >> 1) * 32;
    const int wc   = (warp & 1) * 64;
    const size_t Rb = (size_t)blockIdx.x * 128;
    const int cb   = blockIdx.y * 128;

    float C[2][8][4];
    #pragma unroll
    for (int a = 0; a < 2; ++a)
        #pragma unroll
        for (int b = 0; b < 8; ++b)
            #pragma unroll
            for (int c = 0; c < 4; ++c) C[a][b][c] = 0.f;

    gemm_core<K, NTOT>(Ag, Bg, Rb, cb, As, Bs, C);

    #pragma unroll
    for (int mt = 0; mt < 2; ++mt) {
        const size_t row0 = Rb + wr + mt * 16 + g;
        #pragma unroll
        for (int nt = 0; nt < 8; ++nt) {
            const int col = cb + wc + nt * 8 + 2 * tg;
            float bx = 0.f, by = 0.f;
            if (HASBIAS) { float2 bb = *(const float2*)&bias[col]; bx = bb.x; by = bb.y; }
            float v0 = C[mt][nt][0] + bx, v1 = C[mt][nt][1] + by;
            float v2 = C[mt][nt][2] + bx, v3 = C[mt][nt][3] + by;
            if (RESID) {
                float2 r0v = *(const float2*)&Cg[row0 * NTOT + col];
                float2 r1v = *(const float2*)&Cg[(row0 + 8) * NTOT + col];
                v0 += r0v.x; v1 += r0v.y; v2 += r1v.x; v3 += r1v.y;
            }
            if (RELU) {
                v0 = fmaxf(v0, 0.f); v1 = fmaxf(v1, 0.f);
                v2 = fmaxf(v2, 0.f); v3 = fmaxf(v3, 0.f);
            }
            *(float2*)&Cg[row0 * NTOT + col]       = make_float2(v0, v1);
            *(float2*)&Cg[(row0 + 8) * NTOT + col] = make_float2(v2, v3);
        }
    }
}

// fused RGCN Y-kernel: blockIdx.y selects {W0->Y0, W1->Y1, Wr(+b)->Y2}
__global__ __launch_bounds__(256)
void gemm_y3(const float* __restrict__ Ag,
             const float* __restrict__ W0, const float* __restrict__ W1,
             const float* __restrict__ Wr, const float* __restrict__ rbias)
{
    __shared__ float As[128][20];
    __shared__ float Bs[2][8][136];

    const int which = blockIdx.y;
    const float* Bg = (which == 0) ? W0 : (which == 1) ? W1 : Wr;
    float* Cg       = (which == 0) ? gY0 : (which == 1) ? gY1 : gY2;

    const int tid  = threadIdx.x;
    const int warp = tid >> 5, lane = tid & 31;
    const int g    = lane >> 2, tg = lane & 3;
    const int wr   = (warp >> 1) * 32;
    const int wc   = (warp & 1) * 64;
    const size_t Rb = (size_t)blockIdx.x * 128;

    float C[2][8][4];
    #pragma unroll
    for (int a = 0; a < 2; ++a)
        #pragma unroll
        for (int b = 0; b < 8; ++b)
            #pragma unroll
            for (int c = 0; c < 4; ++c) C[a][b][c] = 0.f;

    gemm_core<Dd, Dd>(Ag, Bg, Rb, 0, As, Bs, C);

    #pragma unroll
    for (int mt = 0; mt < 2; ++mt) {
        const size_t row0 = Rb + wr + mt * 16 + g;
        #pragma unroll
        for (int nt = 0; nt < 8; ++nt) {
            const int col = wc + nt * 8 + 2 * tg;
            float bx = 0.f, by = 0.f;
            if (which == 2) { float2 bb = *(const float2*)&rbias[col]; bx = bb.x; by = bb.y; }
            *(float2*)&Cg[row0 * Dd + col]       = make_float2(C[mt][nt][0] + bx, C[mt][nt][1] + by);
            *(float2*)&Cg[(row0 + 8) * Dd + col] = make_float2(C[mt][nt][2] + bx, C[mt][nt][3] + by);
        }
    }
}

// ---------------- per-graph helper kernels ----------------

__global__ void prep_mix(const float* __restrict__ A)
{
    __shared__ float sA[100];
    __shared__ float r0[Nn], r1[Nn];
    const int b = blockIdx.x, tid = threadIdx.x;   // 32 threads
    for (int i = tid; i < 100; i += 32) sA[i] = A[b * 100 + i];
    __syncwarp();
    if (tid < Nn) {
        int j = tid, c1 = 0;
        #pragma unroll
        for (int i = 0; i < Nn; ++i) c1 += (sA[i * Nn + j] > 0.f);
        r1[j] = 1.f / fmaxf((float)c1, 1.f);
        r0[j] = 1.f / fmaxf((float)(Nn - c1), 1.f);
    }
    __syncwarp();
    if (tid < Nn) {
        const int t = tid;
        float m0[Nn], m1[Nn];
        #pragma unroll
        for (int i = 0; i < Nn; ++i) { m0[i] = 0.f; m1[i] = 0.f; }
        #pragma unroll
        for (int j = 0; j < Nn; ++j) {
            bool pos = sA[t * Nn + j] > 0.f;
            float cf0 = pos ? 0.f : r0[j];
            float cf1 = pos ? r1[j] : 0.f;
            #pragma unroll
            for (int i = 0; i < Nn; ++i) {
                float aij = fabsf(sA[i * Nn + j]);
                m0[i] += aij * cf0;
                m1[i] += aij * cf1;
            }
        }
        float* dst = gMix + (size_t)b * 300;
        #pragma unroll
        for (int i = 0; i < Nn; ++i) {
            dst[      i * Nn + t] = m0[i];
            dst[100 + i * Nn + t] = m1[i];
            dst[200 + i * Nn + t] = fabsf(sA[i * Nn + t]);
        }
    }
}

// agg = relu(LN( M0.Y0 + M1.Y1 + Mr.Y2 ))  per graph, col = tid
__global__ __launch_bounds__(128)
void mix_ln(const float* __restrict__ lng, const float* __restrict__ lnb)
{
    __shared__ float sM[300];
    __shared__ float sAg[Nn][132];
    __shared__ float sMu[Nn], sRs[Nn];
    const int b = blockIdx.x, tid = threadIdx.x;
    const int lane = tid & 31, w = tid >> 5;
    for (int i = tid; i < 300; i += 128) sM[i] = gMix[(size_t)b * 300 + i];
    __syncthreads();

    float acc[Nn];
    #pragma unroll
    for (int i = 0; i < Nn; ++i) acc[i] = 0.f;
    const size_t base = (size_t)b * Nn * Dd + tid;
    #pragma unroll
    for (int s = 0; s < Nn; ++s) {
        float y0 = gY0[base + s * Dd];
        float y1 = gY1[base + s * Dd];
        float y2 = gY2[base + s * Dd];
        #pragma unroll
        for (int i = 0; i < Nn; ++i)
            acc[i] += sM[i * Nn + s] * y0 + sM[100 + i * Nn + s] * y1 + sM[200 + i * Nn + s] * y2;
    }
    #pragma unroll
    for (int i = 0; i < Nn; ++i) sAg[i][tid] = acc[i];
    __syncthreads();

    for (int r = w; r < Nn; r += 4) {
        float s = 0.f, q = 0.f;
        #pragma unroll
        for (int u = 0; u < 4; ++u) {
            float x = sAg[r][lane + 32 * u];
            s += x; q += x * x;
        }
        #pragma unroll
        for (int o = 16; o > 0; o >>= 1) {
            s += __shfl_xor_sync(0xffffffffu, s, o);
            q += __shfl_xor_sync(0xffffffffu, q, o);
        }
        if (lane == 0) {
            float mu = s * (1.f / Dd);
            float var = q * (1.f / Dd) - mu * mu;
            sMu[r] = mu; sRs[r] = rsqrtf(var + EPS);
        }
    }
    __syncthreads();

    const float gt = lng[tid], bt = lnb[tid];
    #pragma unroll
    for (int i = 0; i < Nn; ++i) {
        float y = (acc[i] - sMu[i]) * sRs[i] * gt + bt;
        gAgg[base + i * Dd] = fmaxf(y, 0.f);
    }
}

// masked segment sums -> gS rows [b] = hs, [Bq+b] = aws
__global__ __launch_bounds__(256)
void seg_sum(const int* __restrict__ home)
{
    __shared__ float hm[Nn];
    const int b = blockIdx.x, tid = threadIdx.x;
    if (tid < Nn) hm[tid] = (float)home[b * Nn + tid];
    __syncthreads();
    const size_t base = (size_t)b * Nn * PHId + tid;
    float hs = 0.f, as = 0.f;
    #pragma unroll
    for (int i = 0; i < Nn; ++i) {
        float v = gP2[base + i * PHId];
        float m = hm[i];
        hs += v * m; as += v * (1.f - m);
    }
    gS[(size_t)b * PHId + tid]        = hs;
    gS[(size_t)(Bq + b) * PHId + tid] = as;
}

// out[b] = 0.5 + 0.5*tanh( (rho_h - rho_a) . r2w )
__global__ void final_k(const float* __restrict__ r2w, float* __restrict__ out)
{
    const int b = blockIdx.x, lane = threadIdx.x;   // 32 threads
    float d = 0.f;
    #pragma unroll
    for (int c = lane; c < RHOd; c += 32)
        d += (gR[(size_t)b * RHOd + c] - gR[(size_t)(Bq + b) * RHOd + c]) * r2w[c];
    #pragma unroll
    for (int o = 16; o > 0; o >>= 1) d += __shfl_down_sync(0xffffffffu, d, o);
    if (lane == 0) out[b] = 0.5f + 0.5f * tanhf(d);
}

// ---------------- host ----------------
static float* sym(const void* s) {
    void* p = nullptr;
    cudaGetSymbolAddress(&p, s);
    return (float*)p;
}

extern "C" void kernel_launch(void* const* d_in, const int* in_sizes, int n_in,
                              void* d_out, int out_size)
{
    const float* A    = (const float*)d_in[0];
    const float* X    = (const float*)d_in[1];
    const int*   home = (const int*)  d_in[2];
    const float* We1  = (const float*)d_in[3];
    const float* be1  = (const float*)d_in[4];
    const float* We2  = (const float*)d_in[5];
    const float* be2  = (const float*)d_in[6];
    const float* rgw  = (const float*)d_in[7];
    const float* rgr  = (const float*)d_in[8];
    const float* rgb  = (const float*)d_in[9];
    const float* l1w  = (const float*)d_in[10];
    const float* l1b  = (const float*)d_in[11];
    const float* l2w  = (const float*)d_in[12];
    const float* l2b  = (const float*)d_in[13];
    const float* lng  = (const float*)d_in[14];
    const float* lnb  = (const float*)d_in[15];
    const float* p1w  = (const float*)d_in[16];
    const float* p1b  = (const float*)d_in[17];
    const float* p2w  = (const float*)d_in[18];
    const float* p2b  = (const float*)d_in[19];
    const float* r1w  = (const float*)d_in[20];
    const float* r1b  = (const float*)d_in[21];
    const float* r2w  = (const float*)d_in[22];

    float* pH   = sym(gH);
    float* pT1  = sym(gT1);
    float* pAgg = sym(gAgg);
    float* pP1  = sym(gP1);
    float* pP2  = sym(gP2);
    float* pS   = sym(gS);
    float* pR   = sym(gR);

    const dim3 T(256);
    const dim3 G128(BN / 128, 1);     // 320 CTAs
    const dim3 G256(BN / 128, 2);     // N = 256
    const dim3 GY(BN / 128, 3);       // fused Y0/Y1/Y2
    const dim3 GRHO(2 * Bq / 128, 1); // 64 CTAs

    prep_mix<<<Bq, 32>>>(A);

    // embed
    gemm_tc<DIN, Dd, true,  false, true><<<G128, T>>>(X,   We1, be1, pT1);
    gemm_tc<Dd,  Dd, false, false, true><<<G128, T>>>(pT1, We2, be2, pH);

    for (int l = 0; l < Ll; ++l) {
        gemm_y3<<<GY, T>>>(pH,
                           rgw + (size_t)(l * 2 + 0) * Dd * Dd,
                           rgw + (size_t)(l * 2 + 1) * Dd * Dd,
                           rgr + (size_t)l * Dd * Dd,
                           rgb + l * Dd);
        mix_ln<<<Bq, 128>>>(lng, lnb);
        gemm_tc<Dd, Dd, true,  false, true><<<G128, T>>>(pAgg, l1w + (size_t)l * Dd * Dd, l1b + l * Dd, pT1);
        gemm_tc<Dd, Dd, false, true,  true><<<G128, T>>>(pT1,  l2w + (size_t)l * Dd * Dd, l2b + l * Dd, pH);
    }

    // DeepSet
    gemm_tc<Dd,   PHId, true, false, true><<<G256, T>>>(pH,  p1w, p1b, pP1);
    gemm_tc<PHId, PHId, true, false, true><<<G256, T>>>(pP1, p2w, p2b, pP2);
    seg_sum<<<Bq, 256>>>(home);
    gemm_tc<PHId, RHOd, true, false, true><<<GRHO, T>>>(pS, r1w, r1b, pR);
    final_k<<<Bq, 32>>>(r2w, (float*)d_out);

    (void)in_sizes; (void)n_in; (void)out_size;
}

// round 11
// speedup vs baseline: 1.5271x; 1.1777x over previous
#include <cuda_runtime.h>
#include <math.h>
#include <stdint.h>

#define Bq    4096
#define Nn    10
#define BN    40960
#define DIN   32
#define Dd    128
#define PHId  256
#define RHOd  128
#define Ll    3
#define EPS   1e-5f

// ---------------- scratch ----------------
__device__ float gH  [BN * Dd];
__device__ float gY0 [BN * Dd];
__device__ float gY1 [BN * Dd];
__device__ float gY2 [BN * Dd];
__device__ float gAgg[BN * Dd];
__device__ float gP1 [BN * PHId];
__device__ float gP2 [BN * PHId];
__device__ float gS  [2 * Bq * PHId];
__device__ float gR  [2 * Bq * RHOd];
__device__ float gMix[Bq * 300];

#define ASZ  (128 * 20)     // one A stage (floats)
#define BSZ  (16 * 136)     // one B stage (floats)
#define YLD  132            // fused-intermediate row stride

__device__ __forceinline__ void cpa16(uint32_t d, const void* s) {
    asm volatile("cp.async.ca.shared.global [%0],[%1],16;\n" :: "r"(d), "l"(s));
}
__device__ __forceinline__ void cp_commit() { asm volatile("cp.async.commit_group;\n"); }

__device__ __forceinline__ void mma_tf32(float c[4], uint32_t a0, uint32_t a1, uint32_t a2, uint32_t a3,
                                         uint32_t b0, uint32_t b1) {
    asm("mma.sync.aligned.m16n8k8.row.col.f32.tf32.tf32.f32 "
        "{%0,%1,%2,%3},{%4,%5,%6,%7},{%8,%9},{%0,%1,%2,%3};"
        : "+f"(c[0]), "+f"(c[1]), "+f"(c[2]), "+f"(c[3])
        : "r"(a0), "r"(a1), "r"(a2), "r"(a3), "r"(b0), "r"(b1));
}

// stage chunk ch (A optional) via cp.async; one commit group
template<int K, bool STAGE_A>
__device__ __forceinline__ void issue_stage(const float* __restrict__ Ag, const float* __restrict__ Bg,
                                            int ldb, size_t Rb, int cb, int ch,
                                            float* Asb, float* Bsb, int tid)
{
    if (STAGE_A) {
        const int r = tid >> 1, koff = (tid & 1) * 8;
        const float* src = Ag + (Rb + r) * K + ch * 16 + koff;
        uint32_t d = (uint32_t)__cvta_generic_to_shared(Asb + r * 20 + koff);
        cpa16(d, src); cpa16(d + 16, src + 4);
    }
    {
        const int k = tid >> 4, c = (tid & 15) * 8;
        const float* src = Bg + (size_t)(ch * 16 + k) * ldb + cb + c;
        uint32_t d = (uint32_t)__cvta_generic_to_shared(Bsb + k * 136 + c);
        cpa16(d, src); cpa16(d + 16, src + 4);
    }
    cp_commit();
}

// one 16-k chunk of mma on staged (or smem-resident) operands
__device__ __forceinline__ void compute_chunk(const float* __restrict__ Asb, int lda, int koff0,
                                              const float* __restrict__ Bsb,
                                              int wr, int wc, int g, int tg, float C[2][8][4])
{
    #pragma unroll
    for (int kt = 0; kt < 2; ++kt) {
        uint32_t a[2][4];
        #pragma unroll
        for (int mt = 0; mt < 2; ++mt) {
            const int r0 = wr + mt * 16;
            a[mt][0] = __float_as_uint(Asb[(r0 + g    ) * lda + koff0 + kt * 8 + tg    ]);
            a[mt][1] = __float_as_uint(Asb[(r0 + g + 8) * lda + koff0 + kt * 8 + tg    ]);
            a[mt][2] = __float_as_uint(Asb[(r0 + g    ) * lda + koff0 + kt * 8 + tg + 4]);
            a[mt][3] = __float_as_uint(Asb[(r0 + g + 8) * lda + koff0 + kt * 8 + tg + 4]);
        }
        #pragma unroll
        for (int nt = 0; nt < 8; ++nt) {
            uint32_t b0 = __float_as_uint(Bsb[(kt * 8 + tg    ) * 136 + wc + nt * 8 + g]);
            uint32_t b1 = __float_as_uint(Bsb[(kt * 8 + tg + 4) * 136 + wc + nt * 8 + g]);
            mma_tf32(C[0][nt], a[0][0], a[0][1], a[0][2], a[0][3], b0, b1);
            mma_tf32(C[1][nt], a[1][0], a[1][1], a[1][2], a[1][3], b0, b1);
        }
    }
}

// double-buffered GEMM over K; A from global (STAGE_A) or from smem tile Yb
template<int K, int LDB_, bool STAGE_A>
__device__ __forceinline__ void gemm_db(const float* __restrict__ Ag, const float* __restrict__ Bg,
                                        size_t Rb, int cb,
                                        float* As2, float* Bs2, const float* Yb,
                                        int wr, int wc, int g, int tg, int tid, float C[2][8][4])
{
    constexpr int CH = K / 16;
    issue_stage<K, STAGE_A>(Ag, Bg, LDB_, Rb, cb, 0, As2, Bs2, tid);
    issue_stage<K, STAGE_A>(Ag, Bg, LDB_, Rb, cb, 1 < CH ? 1 : 0, As2 + ASZ, Bs2 + BSZ, tid);
    #pragma unroll 1
    for (int ch = 0; ch < CH; ++ch) {
        if (ch + 1 < CH) asm volatile("cp.async.wait_group 1;\n");
        else             asm volatile("cp.async.wait_group 0;\n");
        __syncthreads();
        const int s = ch & 1;
        if (STAGE_A) compute_chunk(As2 + s * ASZ, 20, 0,       Bs2 + s * BSZ, wr, wc, g, tg, C);
        else         compute_chunk(Yb,           YLD, ch * 16, Bs2 + s * BSZ, wr, wc, g, tg, C);
        __syncthreads();
        if (ch + 2 < CH)
            issue_stage<K, STAGE_A>(Ag, Bg, LDB_, Rb, cb, ch + 2, As2 + s * ASZ, Bs2 + s * BSZ, tid);
    }
}

#define GEMM_IDS \
    const int tid  = threadIdx.x; \
    const int warp = tid >> 5, lane = tid & 31; \
    const int g    = lane >> 2, tg = lane & 3; \
    const int wr   = (warp >> 1) * 32; \
    const int wc   = (warp & 1) * 64; \
    float C[2][8][4]; \
    _Pragma("unroll") for (int _a = 0; _a < 2; ++_a) \
    _Pragma("unroll") for (int _b = 0; _b < 8; ++_b) \
    _Pragma("unroll") for (int _c = 0; _c < 4; ++_c) C[_a][_b][_c] = 0.f;

// ---------------- plain GEMM kernel (phi1/phi2/rho) ----------------
template<int K, int NTOT, bool RELU, bool HASBIAS>
__global__ __launch_bounds__(256)
void gemm_tc(const float* __restrict__ Ag, const float* __restrict__ Bg,
             const float* __restrict__ bias, float* __restrict__ Cg)
{
    __shared__ float As2[2 * ASZ];
    __shared__ float Bs2[2 * BSZ];
    GEMM_IDS
    const size_t Rb = (size_t)blockIdx.x * 128;
    const int cb = blockIdx.y * 128;

    gemm_db<K, NTOT, true>(Ag, Bg, Rb, cb, As2, Bs2, nullptr, wr, wc, g, tg, tid, C);

    #pragma unroll
    for (int mt = 0; mt < 2; ++mt) {
        const size_t row0 = Rb + wr + mt * 16 + g;
        #pragma unroll
        for (int nt = 0; nt < 8; ++nt) {
            const int col = cb + wc + nt * 8 + 2 * tg;
            float bx = 0.f, by = 0.f;
            if (HASBIAS) { float2 bb = *(const float2*)&bias[col]; bx = bb.x; by = bb.y; }
            float v0 = C[mt][nt][0] + bx, v1 = C[mt][nt][1] + by;
            float v2 = C[mt][nt][2] + bx, v3 = C[mt][nt][3] + by;
            if (RELU) { v0 = fmaxf(v0,0.f); v1 = fmaxf(v1,0.f); v2 = fmaxf(v2,0.f); v3 = fmaxf(v3,0.f); }
            *(float2*)&Cg[row0 * NTOT + col]       = make_float2(v0, v1);
            *(float2*)&Cg[(row0 + 8) * NTOT + col] = make_float2(v2, v3);
        }
    }
}

// ---------------- fused RGCN Y kernel ----------------
__global__ __launch_bounds__(256)
void gemm_y3(const float* __restrict__ Ag,
             const float* __restrict__ W0, const float* __restrict__ W1,
             const float* __restrict__ Wr, const float* __restrict__ rbias)
{
    __shared__ float As2[2 * ASZ];
    __shared__ float Bs2[2 * BSZ];
    GEMM_IDS
    const int which = blockIdx.y;
    const float* Bg = (which == 0) ? W0 : (which == 1) ? W1 : Wr;
    float* Cg       = (which == 0) ? gY0 : (which == 1) ? gY1 : gY2;
    const size_t Rb = (size_t)blockIdx.x * 128;

    gemm_db<Dd, Dd, true>(Ag, Bg, Rb, 0, As2, Bs2, nullptr, wr, wc, g, tg, tid, C);

    #pragma unroll
    for (int mt = 0; mt < 2; ++mt) {
        const size_t row0 = Rb + wr + mt * 16 + g;
        #pragma unroll
        for (int nt = 0; nt < 8; ++nt) {
            const int col = wc + nt * 8 + 2 * tg;
            float bx = 0.f, by = 0.f;
            if (which == 2) { float2 bb = *(const float2*)&rbias[col]; bx = bb.x; by = bb.y; }
            *(float2*)&Cg[row0 * Dd + col]       = make_float2(C[mt][nt][0] + bx, C[mt][nt][1] + by);
            *(float2*)&Cg[(row0 + 8) * Dd + col] = make_float2(C[mt][nt][2] + bx, C[mt][nt][3] + by);
        }
    }
}

// ---------------- fused two-GEMM kernels (N=128 full width) ----------------
// out = (relu(A@Wa + ba)) @ Wb + bb [+ residual Hg]; writes Cg
template<int K1, bool RESID>
__global__ __launch_bounds__(256, 2)
void fused2(const float* __restrict__ Ain,
            const float* __restrict__ Wa, const float* __restrict__ ba,
            const float* __restrict__ Wb, const float* __restrict__ bb2,
            float* __restrict__ Cg)
{
    extern __shared__ float sm[];
    float* As2 = sm;                       // 2*ASZ
    float* Bs2 = sm + 2 * ASZ;             // 2*BSZ
    float* Yb  = sm + 2 * ASZ + 2 * BSZ;   // 128*YLD
    GEMM_IDS
    const size_t Rb = (size_t)blockIdx.x * 128;

    gemm_db<K1, Dd, true>(Ain, Wa, Rb, 0, As2, Bs2, nullptr, wr, wc, g, tg, tid, C);

    // epilogue 1: bias + relu -> Yb
    #pragma unroll
    for (int mt = 0; mt < 2; ++mt) {
        const int r0 = wr + mt * 16 + g;
        #pragma unroll
        for (int nt = 0; nt < 8; ++nt) {
            const int col = wc + nt * 8 + 2 * tg;
            float2 bb = *(const float2*)&ba[col];
            *(float2*)&Yb[r0 * YLD + col]       = make_float2(fmaxf(C[mt][nt][0] + bb.x, 0.f),
                                                              fmaxf(C[mt][nt][1] + bb.y, 0.f));
            *(float2*)&Yb[(r0 + 8) * YLD + col] = make_float2(fmaxf(C[mt][nt][2] + bb.x, 0.f),
                                                              fmaxf(C[mt][nt][3] + bb.y, 0.f));
        }
    }
    __syncthreads();

    #pragma unroll
    for (int a = 0; a < 2; ++a)
        #pragma unroll
        for (int b = 0; b < 8; ++b)
            #pragma unroll
            for (int c = 0; c < 4; ++c) C[a][b][c] = 0.f;

    gemm_db<Dd, Dd, false>(nullptr, Wb, Rb, 0, As2, Bs2, Yb, wr, wc, g, tg, tid, C);

    // epilogue 2: bias (+ residual) -> Cg
    #pragma unroll
    for (int mt = 0; mt < 2; ++mt) {
        const size_t row0 = Rb + wr + mt * 16 + g;
        #pragma unroll
        for (int nt = 0; nt < 8; ++nt) {
            const int col = wc + nt * 8 + 2 * tg;
            float2 bb = *(const float2*)&bb2[col];
            float v0 = C[mt][nt][0] + bb.x, v1 = C[mt][nt][1] + bb.y;
            float v2 = C[mt][nt][2] + bb.x, v3 = C[mt][nt][3] + bb.y;
            if (RESID) {
                float2 r0v = *(const float2*)&Cg[row0 * Dd + col];
                float2 r1v = *(const float2*)&Cg[(row0 + 8) * Dd + col];
                v0 += r0v.x; v1 += r0v.y; v2 += r1v.x; v3 += r1v.y;
            }
            *(float2*)&Cg[row0 * Dd + col]       = make_float2(v0, v1);
            *(float2*)&Cg[(row0 + 8) * Dd + col] = make_float2(v2, v3);
        }
    }
}

// ---------------- per-graph helper kernels (unchanged from R10) ----------------
__global__ void prep_mix(const float* __restrict__ A)
{
    __shared__ float sA[100];
    __shared__ float r0[Nn], r1[Nn];
    const int b = blockIdx.x, tid = threadIdx.x;
    for (int i = tid; i < 100; i += 32) sA[i] = A[b * 100 + i];
    __syncwarp();
    if (tid < Nn) {
        int j = tid, c1 = 0;
        #pragma unroll
        for (int i = 0; i < Nn; ++i) c1 += (sA[i * Nn + j] > 0.f);
        r1[j] = 1.f / fmaxf((float)c1, 1.f);
        r0[j] = 1.f / fmaxf((float)(Nn - c1), 1.f);
    }
    __syncwarp();
    if (tid < Nn) {
        const int t = tid;
        float m0[Nn], m1[Nn];
        #pragma unroll
        for (int i = 0; i < Nn; ++i) { m0[i] = 0.f; m1[i] = 0.f; }
        #pragma unroll
        for (int j = 0; j < Nn; ++j) {
            bool pos = sA[t * Nn + j] > 0.f;
            float cf0 = pos ? 0.f : r0[j];
            float cf1 = pos ? r1[j] : 0.f;
            #pragma unroll
            for (int i = 0; i < Nn; ++i) {
                float aij = fabsf(sA[i * Nn + j]);
                m0[i] += aij * cf0;
                m1[i] += aij * cf1;
            }
        }
        float* dst = gMix + (size_t)b * 300;
        #pragma unroll
        for (int i = 0; i < Nn; ++i) {
            dst[      i * Nn + t] = m0[i];
            dst[100 + i * Nn + t] = m1[i];
            dst[200 + i * Nn + t] = fabsf(sA[i * Nn + t]);
        }
    }
}

__global__ __launch_bounds__(128)
void mix_ln(const float* __restrict__ lng, const float* __restrict__ lnb)
{
    __shared__ float sM[300];
    __shared__ float sAg[Nn][132];
    __shared__ float sMu[Nn], sRs[Nn];
    const int b = blockIdx.x, tid = threadIdx.x;
    const int lane = tid & 31, w = tid >> 5;
    for (int i = tid; i < 300; i += 128) sM[i] = gMix[(size_t)b * 300 + i];
    __syncthreads();

    float acc[Nn];
    #pragma unroll
    for (int i = 0; i < Nn; ++i) acc[i] = 0.f;
    const size_t base = (size_t)b * Nn * Dd + tid;
    #pragma unroll
    for (int s = 0; s < Nn; ++s) {
        float y0 = gY0[base + s * Dd];
        float y1 = gY1[base + s * Dd];
        float y2 = gY2[base + s * Dd];
        #pragma unroll
        for (int i = 0; i < Nn; ++i)
            acc[i] += sM[i * Nn + s] * y0 + sM[100 + i * Nn + s] * y1 + sM[200 + i * Nn + s] * y2;
    }
    #pragma unroll
    for (int i = 0; i < Nn; ++i) sAg[i][tid] = acc[i];
    __syncthreads();

    for (int r = w; r < Nn; r += 4) {
        float s = 0.f, q = 0.f;
        #pragma unroll
        for (int u = 0; u < 4; ++u) {
            float x = sAg[r][lane + 32 * u];
            s += x; q += x * x;
        }
        #pragma unroll
        for (int o = 16; o > 0; o >>= 1) {
            s += __shfl_xor_sync(0xffffffffu, s, o);
            q += __shfl_xor_sync(0xffffffffu, q, o);
        }
        if (lane == 0) {
            float mu = s * (1.f / Dd);
            float var = q * (1.f / Dd) - mu * mu;
            sMu[r] = mu; sRs[r] = rsqrtf(var + EPS);
        }
    }
    __syncthreads();

    const float gt = lng[tid], bt = lnb[tid];
    #pragma unroll
    for (int i = 0; i < Nn; ++i) {
        float y = (acc[i] - sMu[i]) * sRs[i] * gt + bt;
        gAgg[base + i * Dd] = fmaxf(y, 0.f);
    }
}

__global__ __launch_bounds__(256)
void seg_sum(const int* __restrict__ home)
{
    __shared__ float hm[Nn];
    const int b = blockIdx.x, tid = threadIdx.x;
    if (tid < Nn) hm[tid] = (float)home[b * Nn + tid];
    __syncthreads();
    const size_t base = (size_t)b * Nn * PHId + tid;
    float hs = 0.f, as = 0.f;
    #pragma unroll
    for (int i = 0; i < Nn; ++i) {
        float v = gP2[base + i * PHId];
        float m = hm[i];
        hs += v * m; as += v * (1.f - m);
    }
    gS[(size_t)b * PHId + tid]        = hs;
    gS[(size_t)(Bq + b) * PHId + tid] = as;
}

__global__ void final_k(const float* __restrict__ r2w, float* __restrict__ out)
{
    const int b = blockIdx.x, lane = threadIdx.x;
    float d = 0.f;
    #pragma unroll
    for (int c = lane; c < RHOd; c += 32)
        d += (gR[(size_t)b * RHOd + c] - gR[(size_t)(Bq + b) * RHOd + c]) * r2w[c];
    #pragma unroll
    for (int o = 16; o > 0; o >>= 1) d += __shfl_down_sync(0xffffffffu, d, o);
    if (lane == 0) out[b] = 0.5f + 0.5f * tanhf(d);
}

// ---------------- host ----------------
static float* sym(const void* s) {
    void* p = nullptr;
    cudaGetSymbolAddress(&p, s);
    return (float*)p;
}

#define SMEM_FUSED ((2 * ASZ + 2 * BSZ + 128 * YLD) * 4)

extern "C" void kernel_launch(void* const* d_in, const int* in_sizes, int n_in,
                              void* d_out, int out_size)
{
    const float* A    = (const float*)d_in[0];
    const float* X    = (const float*)d_in[1];
    const int*   home = (const int*)  d_in[2];
    const float* We1  = (const float*)d_in[3];
    const float* be1  = (const float*)d_in[4];
    const float* We2  = (const float*)d_in[5];
    const float* be2  = (const float*)d_in[6];
    const float* rgw  = (const float*)d_in[7];
    const float* rgr  = (const float*)d_in[8];
    const float* rgb  = (const float*)d_in[9];
    const float* l1w  = (const float*)d_in[10];
    const float* l1b  = (const float*)d_in[11];
    const float* l2w  = (const float*)d_in[12];
    const float* l2b  = (const float*)d_in[13];
    const float* lng  = (const float*)d_in[14];
    const float* lnb  = (const float*)d_in[15];
    const float* p1w  = (const float*)d_in[16];
    const float* p1b  = (const float*)d_in[17];
    const float* p2w  = (const float*)d_in[18];
    const float* p2b  = (const float*)d_in[19];
    const float* r1w  = (const float*)d_in[20];
    const float* r1b  = (const float*)d_in[21];
    const float* r2w  = (const float*)d_in[22];

    float* pH   = sym(gH);
    float* pAgg = sym(gAgg);
    float* pP1  = sym(gP1);
    float* pP2  = sym(gP2);
    float* pS   = sym(gS);
    float* pR   = sym(gR);

    cudaFuncSetAttribute(fused2<DIN, false>, cudaFuncAttributeMaxDynamicSharedMemorySize, SMEM_FUSED);
    cudaFuncSetAttribute(fused2<Dd,  true >, cudaFuncAttributeMaxDynamicSharedMemorySize, SMEM_FUSED);

    const dim3 T(256);
    const dim3 G128(BN / 128, 1);
    const dim3 G256(BN / 128, 2);
    const dim3 GY(BN / 128, 3);
    const dim3 GRHO(2 * Bq / 128, 1);

    prep_mix<<<Bq, 32>>>(A);

    // embed: H = relu(X@We1+be1)@We2 + be2
    fused2<DIN, false><<<G128, T, SMEM_FUSED>>>(X, We1, be1, We2, be2, pH);

    for (int l = 0; l < Ll; ++l) {
        gemm_y3<<<GY, T>>>(pH,
                           rgw + (size_t)(l * 2 + 0) * Dd * Dd,
                           rgw + (size_t)(l * 2 + 1) * Dd * Dd,
                           rgr + (size_t)l * Dd * Dd,
                           rgb + l * Dd);
        mix_ln<<<Bq, 128>>>(lng, lnb);
        // H += relu(agg@l1w+l1b)@l2w + l2b
        fused2<Dd, true><<<G128, T, SMEM_FUSED>>>(pAgg,
                                                  l1w + (size_t)l * Dd * Dd, l1b + l * Dd,
                                                  l2w + (size_t)l * Dd * Dd, l2b + l * Dd,
                                                  pH);
    }

    // DeepSet
    gemm_tc<Dd,   PHId, true, true><<<G256, T>>>(pH,  p1w, p1b, pP1);
    gemm_tc<PHId, PHId, true, true><<<G256, T>>>(pP1, p2w, p2b, pP2);
    seg_sum<<<Bq, 256>>>(home);
    gemm_tc<PHId, RHOd, true, true><<<GRHO, T>>>(pS, r1w, r1b, pR);
    final_k<<<Bq, 32>>>(r2w, (float*)d_out);

    (void)in_sizes; (void)n_in; (void)out_size;
}